// round 12
// baseline (speedup 1.0000x reference)
#include <cuda_runtime.h>
#include <cuda_bf16.h>
#include <math.h>

// ---------------- problem constants ----------------
#define Bz 4
#define LQn 13343          // 100*100+50*50+25*25+13*13+7*7
#define Mrows (Bz * LQn)   // 53372
#define Dm 256
#define Hh 8
#define Ll 5
#define Pp 4
#define HDd 32
#define DFFn 2048

__constant__ int c_Hs[5] = {100, 50, 25, 13, 7};
__constant__ int c_Ws[5] = {100, 50, 25, 13, 7};
__constant__ int c_st[5] = {0, 10000, 12500, 13125, 13294};

// ---------------- scratch (static device globals; no runtime alloc) ----------------
__device__ float g_off   [(size_t)Mrows * 320];   // sampling offsets
__device__ float g_attn  [(size_t)Mrows * 160];   // attn logits -> softmax in place
__device__ float g_val   [(size_t)Mrows * 256];   // value = src @ W_val + b_val
__device__ float g_core  [(size_t)Mrows * 256];   // deformable-attn core output
__device__ float g_proj  [(size_t)Mrows * 256];   // core @ W_out + b_out
__device__ float g_x     [(size_t)Mrows * 256];   // LN1(src + proj)
__device__ float g_hidden[(size_t)Mrows * 2048];  // relu(x @ W1 + bl1)
__device__ float g_ffn   [(size_t)Mrows * 256];   // hidden @ W2 + bl2

// ---------------- generic SGEMM: C = (A (+A2)) @ W + bias, optional relu ----------------
// A: [M,K] row-major, W: [K,N] row-major, bias: [N]. BM=BN=128, BK=8, 256 threads, 8x8/thread.
__global__ void __launch_bounds__(256)
sgemm_kernel(const float* __restrict__ A, const float* __restrict__ A2,
             const float* __restrict__ W, const float* __restrict__ bias,
             float* __restrict__ C, int M, int N, int K, int relu)
{
    __shared__ float As[8][132];   // transposed A tile, padded (132%32==4 -> conflict-free)
    __shared__ float Bs[8][128];

    const int tid = threadIdx.x;
    const int bm = blockIdx.y * 128;
    const int bn = blockIdx.x * 128;
    const int r0 = (tid >> 4) * 8;       // row offset of microtile
    const int c0 = (tid & 15) * 8;       // col offset of microtile

    // A tile loader: 128 rows x 8 cols, one float4 per thread
    const int a_r = tid >> 1;
    const int a_c = (tid & 1) * 4;
    const int a_row = bm + a_r;
    const bool a_ok = (a_row < M);
    const float* Aptr  = A  + (size_t)a_row * K + a_c;
    const float* A2ptr = A2 ? (A2 + (size_t)a_row * K + a_c) : nullptr;

    // B tile loader: 8 rows x 128 cols, one float4 per thread
    const int b_r = tid >> 5;
    const int b_c = (tid & 31) * 4;
    const bool b_ok = (bn + b_c) < N;
    const float* Wptr = W + (size_t)b_r * N + bn + b_c;

    float acc[8][8];
#pragma unroll
    for (int i = 0; i < 8; i++)
#pragma unroll
        for (int j = 0; j < 8; j++) acc[i][j] = 0.f;

    for (int k0 = 0; k0 < K; k0 += 8) {
        float4 av = make_float4(0.f, 0.f, 0.f, 0.f);
        if (a_ok) {
            av = *(const float4*)(Aptr + k0);
            if (A2ptr) {
                float4 a2 = *(const float4*)(A2ptr + k0);
                av.x += a2.x; av.y += a2.y; av.z += a2.z; av.w += a2.w;
            }
        }
        As[a_c + 0][a_r] = av.x;
        As[a_c + 1][a_r] = av.y;
        As[a_c + 2][a_r] = av.z;
        As[a_c + 3][a_r] = av.w;

        float4 bv = make_float4(0.f, 0.f, 0.f, 0.f);
        if (b_ok) bv = *(const float4*)(Wptr + (size_t)k0 * N);
        *(float4*)&Bs[b_r][b_c] = bv;

        __syncthreads();
#pragma unroll
        for (int k = 0; k < 8; k++) {
            float4 a0 = *(const float4*)&As[k][r0];
            float4 a1 = *(const float4*)&As[k][r0 + 4];
            float4 b0 = *(const float4*)&Bs[k][c0];
            float4 b1 = *(const float4*)&Bs[k][c0 + 4];
            float ar[8] = {a0.x, a0.y, a0.z, a0.w, a1.x, a1.y, a1.z, a1.w};
            float br[8] = {b0.x, b0.y, b0.z, b0.w, b1.x, b1.y, b1.z, b1.w};
#pragma unroll
            for (int i = 0; i < 8; i++)
#pragma unroll
                for (int j = 0; j < 8; j++)
                    acc[i][j] = fmaf(ar[i], br[j], acc[i][j]);
        }
        __syncthreads();
    }

#pragma unroll
    for (int i = 0; i < 8; i++) {
        int row = bm + r0 + i;
        if (row < M) {
#pragma unroll
            for (int j = 0; j < 8; j += 4) {
                int col = bn + c0 + j;
                if (col < N) {
                    float4 bb = *(const float4*)(bias + col);
                    float4 v;
                    v.x = acc[i][j + 0] + bb.x;
                    v.y = acc[i][j + 1] + bb.y;
                    v.z = acc[i][j + 2] + bb.z;
                    v.w = acc[i][j + 3] + bb.w;
                    if (relu) {
                        v.x = fmaxf(v.x, 0.f); v.y = fmaxf(v.y, 0.f);
                        v.z = fmaxf(v.z, 0.f); v.w = fmaxf(v.w, 0.f);
                    }
                    *(float4*)(C + (size_t)row * N + col) = v;
                }
            }
        }
    }
}

// ---------------- softmax over the 20 (L*P) logits per (row, head) ----------------
__global__ void softmax20_kernel(int total)
{
    int t = blockIdx.x * blockDim.x + threadIdx.x;
    if (t >= total) return;
    float* p = g_attn + (size_t)t * 20;
    float m = -1e30f;
    float v[20];
#pragma unroll
    for (int i = 0; i < 20; i++) { v[i] = p[i]; m = fmaxf(m, v[i]); }
    float s = 0.f;
#pragma unroll
    for (int i = 0; i < 20; i++) { v[i] = __expf(v[i] - m); s += v[i]; }
    float inv = 1.f / s;
#pragma unroll
    for (int i = 0; i < 20; i++) p[i] = v[i] * inv;
}

// ---------------- deformable attention core: one warp per (row, head), lane = channel ----------------
__global__ void __launch_bounds__(256)
deform_kernel(const float* __restrict__ ref)
{
    int warp = (blockIdx.x * blockDim.x + threadIdx.x) >> 5;
    int lane = threadIdx.x & 31;
    if (warp >= Mrows * Hh) return;
    int row = warp >> 3;          // /H (H=8)
    int h = warp & 7;
    int b = row / LQn;

    const float* offp = g_off  + (size_t)row * 320 + h * 40;   // [lvl*8 + p*2 + xy]
    const float* attp = g_attn + (size_t)row * 160 + h * 20;   // [lvl*4 + p]
    const float* refp = ref    + (size_t)row * (Ll * 2);
    const float* valb = g_val  + (size_t)b * LQn * 256 + h * 32 + lane;

    float acc = 0.f;
#pragma unroll
    for (int lvl = 0; lvl < 5; lvl++) {
        const int W_ = c_Ws[lvl], H_ = c_Hs[lvl], st = c_st[lvl];
        const float fW = (float)W_, fH = (float)H_;
        float rx = refp[lvl * 2 + 0];
        float ry = refp[lvl * 2 + 1];
#pragma unroll
        for (int p = 0; p < 4; p++) {
            float ox = offp[lvl * 8 + p * 2 + 0];
            float oy = offp[lvl * 8 + p * 2 + 1];
            float lx = rx + ox / fW;
            float ly = ry + oy / fH;
            float px = lx * fW - 0.5f;
            float py = ly * fH - 0.5f;
            float x0f = floorf(px), y0f = floorf(py);
            float wx1 = px - x0f, wy1 = py - y0f;
            int x0 = (int)x0f, y0 = (int)y0f;
            float aw = attp[lvl * 4 + p];
            float s = 0.f;
#pragma unroll
            for (int dy = 0; dy < 2; dy++) {
                int yi = y0 + dy;
                if (yi < 0 || yi >= H_) continue;
                float wy = dy ? wy1 : (1.f - wy1);
#pragma unroll
                for (int dx = 0; dx < 2; dx++) {
                    int xi = x0 + dx;
                    if (xi < 0 || xi >= W_) continue;
                    float wx = dx ? wx1 : (1.f - wx1);
                    s = fmaf(wy * wx, valb[(size_t)(st + yi * W_ + xi) * 256], s);
                }
            }
            acc = fmaf(aw, s, acc);
        }
    }
    g_core[(size_t)row * 256 + h * 32 + lane] = acc;
}

// ---------------- fused residual add + LayerNorm: one warp per row (D=256) ----------------
__global__ void __launch_bounds__(256)
add_ln_kernel(const float* __restrict__ a, const float* __restrict__ bb,
              const float* __restrict__ g, const float* __restrict__ beta,
              float* __restrict__ out, int M)
{
    int row = blockIdx.x * 8 + (threadIdx.x >> 5);
    int lane = threadIdx.x & 31;
    if (row >= M) return;
    const float* ap = a + (size_t)row * 256;
    const float* bp = bb + (size_t)row * 256;

    float4 x0 = *(const float4*)(ap + lane * 4);
    float4 x1 = *(const float4*)(ap + 128 + lane * 4);
    float4 y0 = *(const float4*)(bp + lane * 4);
    float4 y1 = *(const float4*)(bp + 128 + lane * 4);
    float v[8] = {x0.x + y0.x, x0.y + y0.y, x0.z + y0.z, x0.w + y0.w,
                  x1.x + y1.x, x1.y + y1.y, x1.z + y1.z, x1.w + y1.w};

    float s = 0.f;
#pragma unroll
    for (int i = 0; i < 8; i++) s += v[i];
#pragma unroll
    for (int o = 16; o; o >>= 1) s += __shfl_xor_sync(0xffffffffu, s, o);
    float mean = s * (1.f / 256.f);

    float vs = 0.f;
#pragma unroll
    for (int i = 0; i < 8; i++) { float d = v[i] - mean; vs += d * d; }
#pragma unroll
    for (int o = 16; o; o >>= 1) vs += __shfl_xor_sync(0xffffffffu, vs, o);
    float rstd = rsqrtf(vs * (1.f / 256.f) + 1e-5f);

    float4 g0 = *(const float4*)(g + lane * 4);
    float4 g1 = *(const float4*)(g + 128 + lane * 4);
    float4 e0 = *(const float4*)(beta + lane * 4);
    float4 e1 = *(const float4*)(beta + 128 + lane * 4);

    float4 o0, o1;
    o0.x = (v[0] - mean) * rstd * g0.x + e0.x;
    o0.y = (v[1] - mean) * rstd * g0.y + e0.y;
    o0.z = (v[2] - mean) * rstd * g0.z + e0.z;
    o0.w = (v[3] - mean) * rstd * g0.w + e0.w;
    o1.x = (v[4] - mean) * rstd * g1.x + e1.x;
    o1.y = (v[5] - mean) * rstd * g1.y + e1.y;
    o1.z = (v[6] - mean) * rstd * g1.z + e1.z;
    o1.w = (v[7] - mean) * rstd * g1.w + e1.w;
    *(float4*)(out + (size_t)row * 256 + lane * 4) = o0;
    *(float4*)(out + (size_t)row * 256 + 128 + lane * 4) = o1;
}

// ---------------- launch ----------------
extern "C" void kernel_launch(void* const* d_in, const int* in_sizes, int n_in,
                              void* d_out, int out_size)
{
    (void)in_sizes; (void)n_in; (void)out_size;
    const float* src   = (const float*)d_in[0];
    const float* pos   = (const float*)d_in[1];
    const float* ref   = (const float*)d_in[2];
    // d_in[3] spatial_shapes, d_in[4] level_start_index: compile-time constants
    const float* W_off = (const float*)d_in[5];
    const float* b_off = (const float*)d_in[6];
    const float* W_att = (const float*)d_in[7];
    const float* b_att = (const float*)d_in[8];
    const float* W_val = (const float*)d_in[9];
    const float* b_val = (const float*)d_in[10];
    const float* W_out = (const float*)d_in[11];
    const float* b_out = (const float*)d_in[12];
    const float* g1    = (const float*)d_in[13];
    const float* beta1 = (const float*)d_in[14];
    const float* W1    = (const float*)d_in[15];
    const float* bl1   = (const float*)d_in[16];
    const float* W2    = (const float*)d_in[17];
    const float* bl2   = (const float*)d_in[18];
    const float* g2    = (const float*)d_in[19];
    const float* beta2 = (const float*)d_in[20];
    float* out = (float*)d_out;

    float *p_off, *p_attn, *p_val, *p_core, *p_proj, *p_x, *p_hid, *p_ffn;
    cudaGetSymbolAddress((void**)&p_off,  g_off);
    cudaGetSymbolAddress((void**)&p_attn, g_attn);
    cudaGetSymbolAddress((void**)&p_val,  g_val);
    cudaGetSymbolAddress((void**)&p_core, g_core);
    cudaGetSymbolAddress((void**)&p_proj, g_proj);
    cudaGetSymbolAddress((void**)&p_x,    g_x);
    cudaGetSymbolAddress((void**)&p_hid,  g_hidden);
    cudaGetSymbolAddress((void**)&p_ffn,  g_ffn);

    const int M = Mrows;
    const int gy = (M + 127) / 128;   // 417
    dim3 thr(256);

    // 1) off = (src+pos) @ W_off + b_off            [M,320]
    sgemm_kernel<<<dim3(3, gy), thr>>>(src, pos, W_off, b_off, p_off, M, 320, 256, 0);
    // 2) attn logits = (src+pos) @ W_attn + b_attn  [M,160]
    sgemm_kernel<<<dim3(2, gy), thr>>>(src, pos, W_att, b_att, p_attn, M, 160, 256, 0);
    // 3) value = src @ W_val + b_val                [M,256]
    sgemm_kernel<<<dim3(2, gy), thr>>>(src, nullptr, W_val, b_val, p_val, M, 256, 256, 0);
    // 4) softmax over 20 per (row, head)
    {
        int total = M * Hh;
        softmax20_kernel<<<(total + 255) / 256, 256>>>(total);
    }
    // 5) deformable attention core                   [M,256]
    deform_kernel<<<(M * Hh + 7) / 8, thr>>>(ref);
    // 6) proj = core @ W_out + b_out                 [M,256]
    sgemm_kernel<<<dim3(2, gy), thr>>>(p_core, nullptr, W_out, b_out, p_proj, M, 256, 256, 0);
    // 7) x = LN1(src + proj)
    add_ln_kernel<<<(M + 7) / 8, thr>>>(src, p_proj, g1, beta1, p_x, M);
    // 8) hidden = relu(x @ W1 + bl1)                 [M,2048]
    sgemm_kernel<<<dim3(16, gy), thr>>>(p_x, nullptr, W1, bl1, p_hid, M, 2048, 256, 1);
    // 9) ffn = hidden @ W2 + bl2                     [M,256]
    sgemm_kernel<<<dim3(2, gy), thr>>>(p_hid, nullptr, W2, bl2, p_ffn, M, 256, 2048, 0);
    // 10) out = LN2(x + ffn)
    add_ln_kernel<<<(M + 7) / 8, thr>>>(p_x, p_ffn, g2, beta2, out, M);
}